// round 16
// baseline (speedup 1.0000x reference)
#include <cuda_runtime.h>
#include <cuda_bf16.h>
#include <cstdint>

// Problem: x[B=256, R=1152, CIN=8] -> A[256 x 9216]
//          W[10,1152,8,16]         -> B[c=n*16+o][k] = [160 x 9216]
//          out[10,256,1,1,16]: s = (1/1152) * A @ B^T, squash over o(16)

#define MB      256
#define KD      9216
#define NC      160
#define W_NSTR  147456
#define KSPLIT  36
#define KCTA    256            // per CTA, as 2 phases of 128
#define MTILE   64

// ---------------- device scratch (static: no allocs) ----------------
__device__ __align__(16) float g_partial[KSPLIT * MB * NC];  // 5.9 MB

// ---------------- helpers ----------------
__device__ __forceinline__ uint32_t smem_u32(const void* p) {
    uint32_t a;
    asm("{ .reg .u64 t; cvta.to.shared.u64 t, %1; cvt.u32.u64 %0, t; }"
        : "=r"(a) : "l"(p));
    return a;
}

__device__ __forceinline__ void ldsm_x4(uint32_t* r, uint32_t addr) {
    asm volatile("ldmatrix.sync.aligned.m8n8.x4.shared.b16 {%0,%1,%2,%3}, [%4];"
                 : "=r"(r[0]), "=r"(r[1]), "=r"(r[2]), "=r"(r[3]) : "r"(addr));
}

__device__ __forceinline__ void mma_bf16(float* d, const uint32_t* a,
                                         uint32_t b0, uint32_t b1) {
    asm volatile(
        "mma.sync.aligned.m16n8k16.row.col.f32.bf16.bf16.f32 "
        "{%0,%1,%2,%3}, {%4,%5,%6,%7}, {%8,%9}, {%0,%1,%2,%3};"
        : "+f"(d[0]), "+f"(d[1]), "+f"(d[2]), "+f"(d[3])
        : "r"(a[0]), "r"(a[1]), "r"(a[2]), "r"(a[3]), "r"(b0), "r"(b1));
}

__device__ __forceinline__ uint32_t pack_bf16(float a, float b) {
    __nv_bfloat162 h = __halves2bfloat162(__float2bfloat16(a), __float2bfloat16(b));
    return *(uint32_t*)&h;
}

// ---------------- fused GEMM: convert + warp-mma (split-K partials) -------
// Skew layout: tile row stride = 272 B; byte(row,k) = row*272 + (k>>3)*16 + (k&7)*2
// bank phase = 16*((row+cs)%8) -> conflict-free fills and ldmatrix.
#define RSTRIDE 272
#define SA_H  0
#define SA_L  17408          // 64*272
#define SB_H  34816
#define SB_L  78336          // +160*272
#define GEMM_SMEM 121856

__global__ void __launch_bounds__(256, 1)
caps_gemm_mma(const float* __restrict__ X, const float* __restrict__ W) {
    extern __shared__ char smem[];
    const uint32_t sb = smem_u32(smem);
    const int t  = threadIdx.x;
    const int mtile = blockIdx.x & 3;                // 4 M tiles of 64
    const int ks    = blockIdx.x >> 2;               // 0..35
    const int M0 = mtile * MTILE;
    const int K0 = ks * KCTA;

    // ---- warp tiling: 8 warps = 4(M=16) x 2(N=80) ----
    const int l  = t & 31;
    const int wid = t >> 5;
    const int wm = wid >> 1;                 // 0..3
    const int wn = wid & 1;                  // 0..1

    float acc[10][4];
#pragma unroll
    for (int nt = 0; nt < 10; ++nt)
#pragma unroll
        for (int q = 0; q < 4; ++q) acc[nt][q] = 0.f;

    // per-lane base addresses (affine in step: +32B per k16-step)
    const int aKh = (l >> 4) & 1;
    const int bKh = (l >> 3) & 1;
    const uint32_t adA = (wm * 16 + (l & 15)) * RSTRIDE + (aKh << 4);
    uint32_t adB[5];
#pragma unroll
    for (int g = 0; g < 5; ++g) {
        int c = wn * 80 + g * 16 + ((l >> 4) & 1) * 8 + (l & 7);
        adB[g] = c * RSTRIDE + (bKh << 4);
    }
    const uint32_t aBase[3] = { sb + SA_H, sb + SA_H, sb + SA_L };
    const uint32_t bBase[3] = { sb + SB_H, sb + SB_L, sb + SB_H };

    for (int kc = 0; kc < 2; ++kc) {
        const int K0p = K0 + kc * 128;

        // ---- fill A: f32 -> bf16 hi/lo (1024 16B chunks: 64 rows x 16) ----
        {
            const float* xb = X + (size_t)M0 * KD + K0p;
#pragma unroll
            for (int it = 0; it < 4; ++it) {
                int u = t + it * 256;
                int row = u >> 4, cs = u & 15;
                const float4* sp = (const float4*)(xb + (size_t)row * KD + cs * 8);
                float4 f0 = sp[0], f1 = sp[1];
                float h0 = __bfloat162float(__float2bfloat16(f0.x));
                float h1 = __bfloat162float(__float2bfloat16(f0.y));
                float h2 = __bfloat162float(__float2bfloat16(f0.z));
                float h3 = __bfloat162float(__float2bfloat16(f0.w));
                float h4 = __bfloat162float(__float2bfloat16(f1.x));
                float h5 = __bfloat162float(__float2bfloat16(f1.y));
                float h6 = __bfloat162float(__float2bfloat16(f1.z));
                float h7 = __bfloat162float(__float2bfloat16(f1.w));
                uint4 H, L;
                H.x = pack_bf16(f0.x, f0.y); H.y = pack_bf16(f0.z, f0.w);
                H.z = pack_bf16(f1.x, f1.y); H.w = pack_bf16(f1.z, f1.w);
                L.x = pack_bf16(f0.x - h0, f0.y - h1);
                L.y = pack_bf16(f0.z - h2, f0.w - h3);
                L.z = pack_bf16(f1.x - h4, f1.y - h5);
                L.w = pack_bf16(f1.z - h6, f1.w - h7);
                uint32_t off = row * RSTRIDE + (cs << 4);
                *(uint4*)(smem + SA_H + off) = H;
                *(uint4*)(smem + SA_L + off) = L;
            }
        }

        // ---- fill B from W: transpose + split (2560 (c,koct) chunks) ----
#pragma unroll
        for (int i = 0; i < 10; ++i) {
            int idx  = t + i * 256;          // 0..2559
            int koct = idx / NC;             // 0..15
            int c    = idx - koct * NC;      // 0..159
            int n = c >> 4, o = c & 15;
            const float* wp = W + (size_t)n * W_NSTR +
                              (size_t)(K0p + koct * 8) * 16 + o;
            float f[8];
#pragma unroll
            for (int j = 0; j < 8; ++j) f[j] = wp[j * 16];
            float h[8];
#pragma unroll
            for (int j = 0; j < 8; ++j)
                h[j] = __bfloat162float(__float2bfloat16(f[j]));
            uint4 H, L;
            H.x = pack_bf16(f[0], f[1]); H.y = pack_bf16(f[2], f[3]);
            H.z = pack_bf16(f[4], f[5]); H.w = pack_bf16(f[6], f[7]);
            L.x = pack_bf16(f[0] - h[0], f[1] - h[1]);
            L.y = pack_bf16(f[2] - h[2], f[3] - h[3]);
            L.z = pack_bf16(f[4] - h[4], f[5] - h[5]);
            L.w = pack_bf16(f[6] - h[6], f[7] - h[7]);
            uint32_t off = c * RSTRIDE + (koct << 4);
            *(uint4*)(smem + SB_H + off) = H;
            *(uint4*)(smem + SB_L + off) = L;
        }
        __syncthreads();

        // ---- MMA: 3 terms x 8 k16-steps x (1 A-frag, 5 B-frags, 10 mma) ----
#pragma unroll
        for (int term = 0; term < 3; ++term) {
            const uint32_t aB = aBase[term], bB = bBase[term];
#pragma unroll
            for (int step = 0; step < 8; ++step) {
                uint32_t af[4], bf[5][4];
                ldsm_x4(af, aB + adA + step * 32);
#pragma unroll
                for (int g = 0; g < 5; ++g)
                    ldsm_x4(bf[g], bB + adB[g] + step * 32);
#pragma unroll
                for (int nt = 0; nt < 10; ++nt) {
                    const int g = nt >> 1, h = nt & 1;
                    mma_bf16(acc[nt], af, bf[g][h * 2], bf[g][h * 2 + 1]);
                }
            }
        }
        __syncthreads();   // smem reuse by next phase
    }

    // ---- epilogue: D fragments -> g_partial[ks][row][c] ----
    float* base = g_partial + (size_t)ks * (MB * NC);
    const int r0 = M0 + wm * 16 + (l >> 2);
#pragma unroll
    for (int nt = 0; nt < 10; ++nt) {
        const int c = wn * 80 + nt * 8 + (l & 3) * 2;
        float2 v0 = make_float2(acc[nt][0], acc[nt][1]);
        float2 v1 = make_float2(acc[nt][2], acc[nt][3]);
        *(float2*)(base + (size_t)r0 * NC + c)       = v0;
        *(float2*)(base + (size_t)(r0 + 8) * NC + c) = v1;
    }
}

// ---------------- reduce + squash (float4, 4 teams of 9 splits) ----------
__global__ void __launch_bounds__(256)
caps_reduce_squash_kernel(float* __restrict__ out) {
    __shared__ float4 sred[4][64];
    const int t    = threadIdx.x;
    const int team = t >> 6;                 // 0..3, 9 splits each
    const int oi   = t & 63;
    const int grp  = blockIdx.x * 64 + oi;   // float4 group id, 0..10239

    float4 acc = make_float4(0.f, 0.f, 0.f, 0.f);
    const float4* src = (const float4*)(g_partial +
                        (size_t)(team * 9) * (MB * NC)) + grp;
#pragma unroll
    for (int s = 0; s < 9; ++s) {
        float4 v = src[(size_t)s * (MB * NC / 4)];
        acc.x += v.x; acc.y += v.y; acc.z += v.z; acc.w += v.w;
    }
    sred[team][oi] = acc;
    __syncthreads();

    if (t < 64) {
        float4 a = sred[0][t], b = sred[1][t], c4 = sred[2][t], d = sred[3][t];
        float4 s;
        s.x = (a.x + b.x + c4.x + d.x) * (1.0f / 1152.0f);
        s.y = (a.y + b.y + c4.y + d.y) * (1.0f / 1152.0f);
        s.z = (a.z + b.z + c4.z + d.z) * (1.0f / 1152.0f);
        s.w = (a.w + b.w + c4.w + d.w) * (1.0f / 1152.0f);

        // squash over 16 o's = quad of threads x 4 floats
        float sq = s.x * s.x + s.y * s.y + s.z * s.z + s.w * s.w;
        sq += __shfl_xor_sync(0xFFFFFFFFu, sq, 1);
        sq += __shfl_xor_sync(0xFFFFFFFFu, sq, 2);
        const float scale = sqrtf(sq) / (1.0f + sq);

        const int g    = blockIdx.x * 64 + t;
        const int flat = g * 4;              // b*160 + c, c = n*16+o
        const int b0   = flat / NC;
        const int c0   = flat - b0 * NC;
        const int n    = c0 >> 4, o = c0 & 15;
        float4 v;
        v.x = s.x * scale; v.y = s.y * scale;
        v.z = s.z * scale; v.w = s.w * scale;
        *(float4*)(out + n * (MB * 16) + b0 * 16 + o) = v;
    }
}

// ---------------- launch ----------------
extern "C" void kernel_launch(void* const* d_in, const int* in_sizes, int n_in,
                              void* d_out, int out_size) {
    const float* X  = (const float*)d_in[0];
    const float* Wt = (const float*)d_in[1];
    if (n_in >= 2 && in_sizes[0] == 10 * 1152 * 8 * 16) {
        const float* tmp = X; X = Wt; Wt = tmp;     // defensive order check
    }

    cudaFuncSetAttribute(caps_gemm_mma,
                         cudaFuncAttributeMaxDynamicSharedMemorySize,
                         GEMM_SMEM);

    caps_gemm_mma<<<4 * KSPLIT, 256, GEMM_SMEM>>>(X, Wt);
    caps_reduce_squash_kernel<<<(MB * NC) / 256, 256>>>((float*)d_out);
}